// round 16
// baseline (speedup 1.0000x reference)
#include <cuda_runtime.h>
#include <cuda_fp16.h>
#include <math.h>
#include <stdint.h>

#define NN     50000
#define EE     200000
#define HEADS  4
#define GG     512
#define HID    1024
#define OUTD   128
#define D1     78
#define D2     312
#define D3     1248
#define NEG    0.2f
#define K1PAD  80
#define NP1    320
#define NP23   1256

__device__ __align__(16) __half g_bufA_h[(size_t)NN * D3];
__device__ __align__(16) __half g_bufB_h[(size_t)NN * NP23];
__device__ __align__(16) __half g_xpad_h[(size_t)NN * K1PAD];
__device__ __align__(16) __half g_pool_h[GG * D3];
__device__ __align__(16) __half g_fc1_h[GG * HID];
__device__ __align__(16) uint32_t g_w1p[(K1PAD / 2) * NP1];
__device__ __align__(16) uint32_t g_w2p[(D2 / 2) * NP23];
__device__ __align__(16) uint32_t g_w3p[(size_t)(D3 / 2) * NP23];
__device__ __align__(16) uint32_t g_fc1p[(D3 / 2) * HID];
__device__ __align__(16) uint32_t g_fc2p[(HID / 2) * OUTD];
__device__ int   g_counts[NN];
__device__ int   g_cursor[NN];
__device__ int   g_ptr[NN + 1];
__device__ int   g_csrsrc[EE];

__device__ __forceinline__ float lrelu(float x) { return x > 0.f ? x : NEG * x; }

__device__ __forceinline__ const __half* sel_h(int s) {
    switch (s) {
        case 1: return g_bufA_h;
        case 2: return g_bufB_h;
        case 3: return g_pool_h;
        case 4: return g_fc1_h;
        case 5: return g_xpad_h;
        default: return g_bufA_h;
    }
}
__device__ __forceinline__ __half* sel_hw(int s) {
    switch (s) {
        case 1: return g_bufA_h;
        case 2: return g_bufB_h;
        case 3: return g_pool_h;
        case 4: return g_fc1_h;
        default: return g_bufA_h;
    }
}
__device__ __forceinline__ const uint32_t* sel_w(int s) {
    switch (s) {
        case 7:  return g_w1p;
        case 8:  return g_w2p;
        case 9:  return g_w3p;
        case 10: return g_fc1p;
        default: return g_fc2p;
    }
}

// ---------------- CSR ----------------
__global__ void zero_counts_kernel() {
    int i = blockIdx.x * blockDim.x + threadIdx.x;
    if (i < NN) { g_counts[i] = 0; g_cursor[i] = 0; }
}
__global__ void hist_kernel(const int* __restrict__ ei) {
    int e = blockIdx.x * blockDim.x + threadIdx.x;
    if (e < EE) atomicAdd(&g_counts[ei[EE + e]], 1);
}
__global__ void scan_kernel() {
    __shared__ int sh[1024];
    __shared__ int s_off;
    int tid = threadIdx.x;
    if (tid == 0) { s_off = 0; g_ptr[0] = 0; }
    __syncthreads();
    for (int base = 0; base < NN; base += 1024) {
        int v = (base + tid < NN) ? g_counts[base + tid] : 0;
        sh[tid] = v;
        __syncthreads();
        for (int s = 1; s < 1024; s <<= 1) {
            int t = (tid >= s) ? sh[tid - s] : 0;
            __syncthreads();
            sh[tid] += t;
            __syncthreads();
        }
        int off = s_off;
        if (base + tid < NN) g_ptr[base + tid + 1] = off + sh[tid];
        __syncthreads();
        if (tid == 0) s_off = off + sh[1023];
        __syncthreads();
    }
}
__global__ void csr_fill_kernel(const int* __restrict__ ei) {
    int e = blockIdx.x * blockDim.x + threadIdx.x;
    if (e < EE) {
        int r = ei[e];
        int c = ei[EE + e];
        int pos = g_ptr[c] + atomicAdd(&g_cursor[c], 1);
        g_csrsrc[pos] = r;
    }
}

// ---------------- fused operand prep ----------------
#define S0 (NN * K1PAD)
#define S1 ((K1PAD / 2) * 312)
#define S2 ((D2 / 2) * D3)
#define S3 ((D3 / 2) * D3)
#define S4 ((D3 / 2) * HID)
#define S5 ((HID / 2) * OUTD)
#define PREP_TOTAL (S0 + S1 + S2 + S3 + S4 + S5)

__device__ __forceinline__ void pack_one(const float* W, uint32_t* dst,
                                         int idx, int KREAL, int N, int NP) {
    int kk = idx / N, n = idx - kk * N;
    float v0 = (2 * kk     < KREAL) ? W[(size_t)(2 * kk) * N + n] : 0.f;
    float v1 = (2 * kk + 1 < KREAL) ? W[(size_t)(2 * kk + 1) * N + n] : 0.f;
    __half2 h = __floats2half2_rn(v0, v1);
    dst[(size_t)kk * NP + n] = *(uint32_t*)&h;
}

__global__ void prep_pack(const float* __restrict__ x,
                          const float* __restrict__ W1,
                          const float* __restrict__ W2,
                          const float* __restrict__ W3,
                          const float* __restrict__ fc1w,
                          const float* __restrict__ fc2w)
{
    int idx = blockIdx.x * blockDim.x + threadIdx.x;
    if (idx < S0) {
        int n = idx / K1PAD, k = idx - n * K1PAD;
        g_xpad_h[idx] = __float2half_rn((k < D1) ? x[(size_t)n * D1 + k] : 0.f);
        return;
    }
    idx -= S0;
    if (idx < S1) { pack_one(W1, g_w1p, idx, D1, 312, NP1); return; }
    idx -= S1;
    if (idx < S2) { pack_one(W2, g_w2p, idx, D2, D3, NP23); return; }
    idx -= S2;
    if (idx < S3) { pack_one(W3, g_w3p, idx, D3, D3, NP23); return; }
    idx -= S3;
    if (idx < S4) { pack_one(fc1w, g_fc1p, idx, D3, HID, HID); return; }
    idx -= S4;
    if (idx < S5) { pack_one(fc2w, g_fc2p, idx, HID, OUTD, OUTD); }
}

#define WS1 (((K1PAD / 2)) * 8)
#define WS2 (((D2 / 2)) * 8)
#define WS3 (((D3 / 2)) * 8)
#define WS_TOTAL (WS1 + WS2 + WS3)

__global__ void ws_all(const float* __restrict__ W1,
                       const float* __restrict__ as1, const float* __restrict__ ad1,
                       const float* __restrict__ W2,
                       const float* __restrict__ as2, const float* __restrict__ ad2,
                       const float* __restrict__ W3,
                       const float* __restrict__ as3, const float* __restrict__ ad3)
{
    int warp = (blockIdx.x * blockDim.x + threadIdx.x) >> 5;
    int lane = threadIdx.x & 31;
    if (warp >= WS_TOTAL) return;

    const float *W, *att_s, *att_d;
    uint32_t* dst;
    int C, H, N, NP, KREAL, w;
    if (warp < WS1) {
        w = warp; W = W1; att_s = as1; att_d = ad1;
        C = D1; H = HEADS; N = 312; NP = NP1; KREAL = D1;
        dst = g_w1p;
    } else if (warp < WS1 + WS2) {
        w = warp - WS1; W = W2; att_s = as2; att_d = ad2;
        C = D2; H = HEADS; N = D3; NP = NP23; KREAL = D2;
        dst = g_w2p;
    } else {
        w = warp - WS1 - WS2; W = W3; att_s = as3; att_d = ad3;
        C = D3; H = 1; N = D3; NP = NP23; KREAL = D3;
        dst = g_w3p;
    }
    int kk = w >> 3, slot = w & 7;
    int h = slot & 3;
    const float* att = (slot >= 4) ? att_d : att_s;

    float v0 = 0.f, v1 = 0.f;
    if (h < H) {
        const float* ar = att + h * C;
        const float* w0 = W + (size_t)(2 * kk) * N + h * C;
        const float* w1 = W + (size_t)(2 * kk + 1) * N + h * C;
        bool ok0 = (2 * kk < KREAL), ok1 = (2 * kk + 1 < KREAL);
        for (int c = lane; c < C; c += 32) {
            float a = ar[c];
            if (ok0) v0 = fmaf(w0[c], a, v0);
            if (ok1) v1 = fmaf(w1[c], a, v1);
        }
#pragma unroll
        for (int o = 16; o; o >>= 1) {
            v0 += __shfl_down_sync(0xFFFFFFFFu, v0, o);
            v1 += __shfl_down_sync(0xFFFFFFFFu, v1, o);
        }
    }
    if (lane == 0) {
        __half2 hp = __floats2half2_rn(v0, v1);
        dst[(size_t)kk * NP + N + slot] = *(uint32_t*)&hp;
    }
}

// ---------------- FP16 GEMM (mma.m16n8k16, cp.async, ldmatrix A) -----------
// Warp tiling: 2m x 4n warp grid, 64x32 warp tile (B fragments reused 4x).
__device__ __forceinline__ void mma_fp16(float c[4], const uint32_t a[4],
                                         uint32_t b0, uint32_t b1)
{
    asm volatile(
        "mma.sync.aligned.m16n8k16.row.col.f32.f16.f16.f32 "
        "{%0,%1,%2,%3}, {%4,%5,%6,%7}, {%8,%9}, {%0,%1,%2,%3};"
        : "+f"(c[0]), "+f"(c[1]), "+f"(c[2]), "+f"(c[3])
        : "r"(a[0]), "r"(a[1]), "r"(a[2]), "r"(a[3]), "r"(b0), "r"(b1));
}

#define CA_AP    20
#define CA_ASZ   (128 * CA_AP)
#define CA_BP    136
#define CA_BSZ   (16 * CA_BP)
#define CA_STW   (CA_ASZ + CA_BSZ)
#define CA_SMEM_BYTES (3 * CA_STW * 4)

template<int FUSE, int OUTF32>
__global__ void __launch_bounds__(256)
hgemm_ca(int Asel, int Bsel, float* Cext, int Csel, int M, int N, int K,
         const float* __restrict__ bias)
{
    extern __shared__ uint32_t smw[];
    uint32_t sb = (uint32_t)__cvta_generic_to_shared(smw);

    const __half* A = sel_h(Asel);
    const uint32_t* Bp = sel_w(Bsel);
    __half* Ch = sel_hw(Csel);

    int tid = threadIdx.x;
    int warpid = tid >> 5, lane = tid & 31;
    int bm = blockIdx.y * 128, bn = blockIdx.x * 128;
    int wm = (warpid >> 2) * 64;         // 2 m-groups of 64
    int wn = (warpid & 3) * 32;          // 4 n-groups of 32
    int grp = lane >> 2, tig = lane & 3;

    int lm_row = (lane & 7) + ((lane >> 3) & 1) * 8;
    int lm_kw  = ((lane >> 4) & 1) * 4;

    float cacc[4][4][4];
#pragma unroll
    for (int mf = 0; mf < 4; mf++)
#pragma unroll
        for (int nf = 0; nf < 4; nf++)
#pragma unroll
            for (int q = 0; q < 4; q++) cacc[mf][nf][q] = 0.f;

    int steps = (K + 31) >> 5;
    int K2 = K >> 1;

    auto issue = [&](int st, int k0) {
        uint32_t abase = sb + (uint32_t)(st * CA_STW) * 4;
        uint32_t bbase = abase + CA_ASZ * 4;
#pragma unroll
        for (int q = 0; q < 2; q++) {
            int flat = q * 256 + tid;
            int row = flat >> 2, kc = (flat & 3) * 8;
            int gm = bm + row, gk = k0 + kc;
            bool p = (gm < M) && (gk < K);
            const __half* src = p ? (A + (size_t)gm * K + gk) : A;
            uint32_t dst = abase + (uint32_t)(row * CA_AP + (kc >> 1)) * 4;
            uint32_t sz = p ? 16u : 0u;
            asm volatile("cp.async.cg.shared.global [%0], [%1], 16, %2;"
                         :: "r"(dst), "l"(src), "r"(sz));
        }
#pragma unroll
        for (int q = 0; q < 2; q++) {
            int flat = q * 256 + tid;
            int kkw = flat >> 5, n4 = (flat & 31) * 4;
            int gkk = (k0 >> 1) + kkw, gn = bn + n4;
            bool p = (gkk < K2) && (gn < N);
            const uint32_t* src = p ? (Bp + (size_t)gkk * N + gn) : Bp;
            uint32_t dst = bbase + (uint32_t)(kkw * CA_BP + n4) * 4;
            uint32_t sz = p ? 16u : 0u;
            asm volatile("cp.async.cg.shared.global [%0], [%1], 16, %2;"
                         :: "r"(dst), "l"(src), "r"(sz));
        }
        asm volatile("cp.async.commit_group;");
    };

    issue(0, 0);
    if (steps > 1) issue(1, 32);

    for (int s = 0; s < steps; s++) {
        int buf = s % 3;
        if (s + 1 < steps) asm volatile("cp.async.wait_group 1;");
        else               asm volatile("cp.async.wait_group 0;");
        __syncthreads();
        if (s + 2 < steps) issue((s + 2) % 3, (s + 2) << 5);

        uint32_t abase = sb + (uint32_t)(buf * CA_STW) * 4;
        const uint32_t* bs = smw + buf * CA_STW + CA_ASZ;
#pragma unroll
        for (int kf = 0; kf < 2; kf++) {
            int kw = kf * 8;
            uint32_t af[4][4];
#pragma unroll
            for (int mf = 0; mf < 4; mf++) {
                int m0 = wm + mf * 16;
                uint32_t aaddr = abase +
                    (uint32_t)((m0 + lm_row) * CA_AP + kw + lm_kw) * 4;
                asm volatile(
                    "ldmatrix.sync.aligned.m8n8.x4.shared.b16 {%0,%1,%2,%3}, [%4];"
                    : "=r"(af[mf][0]), "=r"(af[mf][1]),
                      "=r"(af[mf][2]), "=r"(af[mf][3])
                    : "r"(aaddr));
            }
#pragma unroll
            for (int nf = 0; nf < 4; nf++) {
                int n0 = wn + nf * 8 + grp;
                uint32_t b0 = bs[(kw + tig    ) * CA_BP + n0];
                uint32_t b1 = bs[(kw + tig + 4) * CA_BP + n0];
                mma_fp16(cacc[0][nf], af[0], b0, b1);
                mma_fp16(cacc[1][nf], af[1], b0, b1);
                mma_fp16(cacc[2][nf], af[2], b0, b1);
                mma_fp16(cacc[3][nf], af[3], b0, b1);
            }
        }
    }

#pragma unroll
    for (int mf = 0; mf < 4; mf++) {
#pragma unroll
        for (int nf = 0; nf < 4; nf++) {
            int r0 = bm + wm + mf * 16 + grp;
            int c0 = bn + wn + nf * 8 + tig * 2;
            float c[4] = { cacc[mf][nf][0], cacc[mf][nf][1],
                           cacc[mf][nf][2], cacc[mf][nf][3] };
            if (FUSE) {
                float b0 = (c0     < N) ? bias[c0]     : 0.f;
                float b1 = (c0 + 1 < N) ? bias[c0 + 1] : 0.f;
                c[0] = fmaxf(c[0] + b0, 0.f);
                c[1] = fmaxf(c[1] + b1, 0.f);
                c[2] = fmaxf(c[2] + b0, 0.f);
                c[3] = fmaxf(c[3] + b1, 0.f);
            }
            if (c0 < N) {
                if (OUTF32) {
                    if (r0 < M)     *(float2*)&Cext[(size_t)r0 * N + c0] = make_float2(c[0], c[1]);
                    if (r0 + 8 < M) *(float2*)&Cext[(size_t)(r0 + 8) * N + c0] = make_float2(c[2], c[3]);
                } else {
                    if (r0 < M) {
                        __half2 h = __floats2half2_rn(c[0], c[1]);
                        *(uint32_t*)&Ch[(size_t)r0 * N + c0] = *(uint32_t*)&h;
                    }
                    if (r0 + 8 < M) {
                        __half2 h = __floats2half2_rn(c[2], c[3]);
                        *(uint32_t*)&Ch[(size_t)(r0 + 8) * N + c0] = *(uint32_t*)&h;
                    }
                }
            }
        }
    }
}

// ---------------- GAT aggregation (fp16 rows, 2-edge pipeline) -------------
template<int H, int C, int NP, int NV, int TPB>
__global__ void __launch_bounds__(TPB)
gat_agg_h(const float* __restrict__ bias)
{
    constexpr int HC  = H * C;
    constexpr int HC8 = HC / 8;
    constexpr int CHUNK = 64;
    int i = blockIdx.x;
    int tid = threadIdx.x;

    __shared__ float s_sc[CHUNK][4];
    __shared__ float s_alpha[CHUNK][4];
    __shared__ int   s_src[CHUNK];

    const __half* hbuf = g_bufB_h;
    __half* out = g_bufA_h;
    const __half* row = hbuf + (size_t)i * NP;

    float scS[4], scD[4];
    {
        uint4 v = *(const uint4*)&row[HC];
        __half2* p = (__half2*)&v;
        float2 f0 = __half22float2(p[0]), f1 = __half22float2(p[1]);
        float2 f2 = __half22float2(p[2]), f3 = __half22float2(p[3]);
        scS[0] = f0.x; scS[1] = f0.y; scS[2] = f1.x; scS[3] = f1.y;
        scD[0] = f2.x; scD[1] = f2.y; scD[2] = f3.x; scD[3] = f3.y;
    }

    float adsti[H], m[H], den[H], eself[H], aself[H];
#pragma unroll
    for (int h = 0; h < H; h++) {
        adsti[h] = scD[h];
        eself[h] = lrelu(scS[h] + adsti[h]);
        m[h] = eself[h];
        den[h] = 1.f;
    }

    int beg = g_ptr[i];
    int deg = g_ptr[i + 1] - beg;
    bool single = (deg <= CHUNK);

    for (int cb = 0; cb < deg; cb += CHUNK) {
        int cn = min(CHUNK, deg - cb);
        for (int t = tid; t < cn; t += TPB) {
            int s = g_csrsrc[beg + cb + t];
            s_src[t] = s;
            uint2 v = *(const uint2*)&hbuf[(size_t)s * NP + HC];
            __half2* p = (__half2*)&v;
            float2 f0 = __half22float2(p[0]), f1 = __half22float2(p[1]);
            s_sc[t][0] = f0.x; s_sc[t][1] = f0.y;
            s_sc[t][2] = f1.x; s_sc[t][3] = f1.y;
        }
        __syncthreads();
        for (int j = 0; j < cn; j++) {
#pragma unroll
            for (int h = 0; h < H; h++) {
                float e = lrelu(s_sc[j][h] + adsti[h]);
                float mo = m[h];
                float mn = fmaxf(mo, e);
                den[h] = den[h] * __expf(mo - mn) + __expf(e - mn);
                m[h] = mn;
            }
        }
        __syncthreads();
    }
#pragma unroll
    for (int h = 0; h < H; h++)
        aself[h] = __expf(eself[h] - m[h]) / (den[h] + 1e-16f);

    int c8i[NV];
    bool val[NV];
    int he[NV][8];
#pragma unroll
    for (int t = 0; t < NV; t++) {
        int c8 = tid + t * TPB;
        c8i[t] = c8;
        val[t] = (c8 < HC8);
#pragma unroll
        for (int e = 0; e < 8; e++)
            he[t][e] = min((c8 * 8 + e) / C, H - 1);
    }

    float acc[NV][8];
#pragma unroll
    for (int t = 0; t < NV; t++) {
        if (val[t]) {
            uint4 v = *(const uint4*)&row[c8i[t] * 8];
            __half2* p = (__half2*)&v;
            float2 q0 = __half22float2(p[0]), q1 = __half22float2(p[1]);
            float2 q2 = __half22float2(p[2]), q3 = __half22float2(p[3]);
            float f[8] = { q0.x, q0.y, q1.x, q1.y, q2.x, q2.y, q3.x, q3.y };
#pragma unroll
            for (int e = 0; e < 8; e++) acc[t][e] = aself[he[t][e]] * f[e];
        } else {
#pragma unroll
            for (int e = 0; e < 8; e++) acc[t][e] = 0.f;
        }
    }

    for (int cb = 0; cb < deg; cb += CHUNK) {
        int cn = min(CHUNK, deg - cb);
        __syncthreads();
        if (!single) {
            for (int t = tid; t < cn; t += TPB) {
                int s = g_csrsrc[beg + cb + t];
                s_src[t] = s;
                uint2 v = *(const uint2*)&hbuf[(size_t)s * NP + HC];
                __half2* p = (__half2*)&v;
                float2 f0 = __half22float2(p[0]), f1 = __half22float2(p[1]);
                s_sc[t][0] = f0.x; s_sc[t][1] = f0.y;
                s_sc[t][2] = f1.x; s_sc[t][3] = f1.y;
            }
            __syncthreads();
        }
        for (int t = tid; t < cn; t += TPB) {
#pragma unroll
            for (int h = 0; h < H; h++) {
                float e = lrelu(s_sc[t][h] + adsti[h]);
                s_alpha[t][h] = __expf(e - m[h]) / (den[h] + 1e-16f);
            }
        }
        __syncthreads();

        uint4 nxt0[NV], nxt1[NV];
        {
            const uint4* h0p = (const uint4*)(hbuf + (size_t)s_src[0] * NP);
            const uint4* h1p = (const uint4*)(hbuf + (size_t)s_src[cn > 1 ? 1 : 0] * NP);
#pragma unroll
            for (int t = 0; t < NV; t++) {
                if (val[t]) { nxt0[t] = h0p[c8i[t]]; nxt1[t] = h1p[c8i[t]]; }
            }
        }
        for (int j = 0; j < cn; j += 2) {
            uint4 cur0[NV], cur1[NV];
#pragma unroll
            for (int t = 0; t < NV; t++) { cur0[t] = nxt0[t]; cur1[t] = nxt1[t]; }
            if (j + 2 < cn) {
                const uint4* h0p = (const uint4*)(hbuf + (size_t)s_src[j + 2] * NP);
                const uint4* h1p = (const uint4*)(hbuf + (size_t)s_src[j + 3 < cn ? j + 3 : j + 2] * NP);
#pragma unroll
                for (int t = 0; t < NV; t++) {
                    if (val[t]) { nxt0[t] = h0p[c8i[t]]; nxt1[t] = h1p[c8i[t]]; }
                }
            }
            {
                float a0 = s_alpha[j][0];
                float a1 = (H > 1) ? s_alpha[j][1] : a0;
                float a2 = (H > 2) ? s_alpha[j][2] : a0;
                float a3 = (H > 3) ? s_alpha[j][3] : a0;
                float al[4] = { a0, a1, a2, a3 };
#pragma unroll
                for (int t = 0; t < NV; t++) {
                    if (!val[t]) continue;
                    __half2* p = (__half2*)&cur0[t];
                    float2 q0 = __half22float2(p[0]), q1 = __half22float2(p[1]);
                    float2 q2 = __half22float2(p[2]), q3 = __half22float2(p[3]);
                    float f[8] = { q0.x, q0.y, q1.x, q1.y, q2.x, q2.y, q3.x, q3.y };
#pragma unroll
                    for (int e = 0; e < 8; e++)
                        acc[t][e] = fmaf(al[he[t][e]], f[e], acc[t][e]);
                }
            }
            if (j + 1 < cn) {
                float a0 = s_alpha[j + 1][0];
                float a1 = (H > 1) ? s_alpha[j + 1][1] : a0;
                float a2 = (H > 2) ? s_alpha[j + 1][2] : a0;
                float a3 = (H > 3) ? s_alpha[j + 1][3] : a0;
                float al[4] = { a0, a1, a2, a3 };
#pragma unroll
                for (int t = 0; t < NV; t++) {
                    if (!val[t]) continue;
                    __half2* p = (__half2*)&cur1[t];
                    float2 q0 = __half22float2(p[0]), q1 = __half22float2(p[1]);
                    float2 q2 = __half22float2(p[2]), q3 = __half22float2(p[3]);
                    float f[8] = { q0.x, q0.y, q1.x, q1.y, q2.x, q2.y, q3.x, q3.y };
#pragma unroll
                    for (int e = 0; e < 8; e++)
                        acc[t][e] = fmaf(al[he[t][e]], f[e], acc[t][e]);
                }
            }
        }
    }

    __half* orow = out + (size_t)i * HC;
#pragma unroll
    for (int t = 0; t < NV; t++) {
        if (!val[t]) continue;
        int cb0 = c8i[t] * 8;
        float4 b0 = *(const float4*)&bias[cb0];
        float4 b1 = *(const float4*)&bias[cb0 + 4];
        float o[8];
        o[0] = fmaxf(acc[t][0] + b0.x, 0.f);
        o[1] = fmaxf(acc[t][1] + b0.y, 0.f);
        o[2] = fmaxf(acc[t][2] + b0.z, 0.f);
        o[3] = fmaxf(acc[t][3] + b0.w, 0.f);
        o[4] = fmaxf(acc[t][4] + b1.x, 0.f);
        o[5] = fmaxf(acc[t][5] + b1.y, 0.f);
        o[6] = fmaxf(acc[t][6] + b1.z, 0.f);
        o[7] = fmaxf(acc[t][7] + b1.w, 0.f);
        uint4 ov;
        __half2 h0 = __floats2half2_rn(o[0], o[1]);
        __half2 h1 = __floats2half2_rn(o[2], o[3]);
        __half2 h2 = __floats2half2_rn(o[4], o[5]);
        __half2 h3 = __floats2half2_rn(o[6], o[7]);
        ov.x = *(uint32_t*)&h0; ov.y = *(uint32_t*)&h1;
        ov.z = *(uint32_t*)&h2; ov.w = *(uint32_t*)&h3;
        *(uint4*)&orow[cb0] = ov;
    }
}

// ---------------- pool ----------------
__global__ void pool_max(const int* __restrict__ batch)
{
    int g = blockIdx.x;
    int c8 = blockIdx.y * 128 + threadIdx.x;

    int lo = 0, hi = NN;
    while (lo < hi) { int mid = (lo + hi) >> 1; if (batch[mid] < g) lo = mid + 1; else hi = mid; }
    int start = lo;
    lo = start; hi = NN;
    while (lo < hi) { int mid = (lo + hi) >> 1; if (batch[mid] < g + 1) lo = mid + 1; else hi = mid; }
    int end = lo;

    if (c8 < D3 / 8) {
        float mv[8];
#pragma unroll
        for (int e = 0; e < 8; e++) mv[e] = 0.f;
        for (int n = start; n < end; n++) {
            uint4 v = *(const uint4*)&g_bufA_h[(size_t)n * D3 + c8 * 8];
            __half2* p = (__half2*)&v;
            float2 q0 = __half22float2(p[0]), q1 = __half22float2(p[1]);
            float2 q2 = __half22float2(p[2]), q3 = __half22float2(p[3]);
            mv[0] = fmaxf(mv[0], q0.x); mv[1] = fmaxf(mv[1], q0.y);
            mv[2] = fmaxf(mv[2], q1.x); mv[3] = fmaxf(mv[3], q1.y);
            mv[4] = fmaxf(mv[4], q2.x); mv[5] = fmaxf(mv[5], q2.y);
            mv[6] = fmaxf(mv[6], q3.x); mv[7] = fmaxf(mv[7], q3.y);
        }
        uint4 ov;
        __half2 h0 = __floats2half2_rn(mv[0], mv[1]);
        __half2 h1 = __floats2half2_rn(mv[2], mv[3]);
        __half2 h2 = __floats2half2_rn(mv[4], mv[5]);
        __half2 h3 = __floats2half2_rn(mv[6], mv[7]);
        ov.x = *(uint32_t*)&h0; ov.y = *(uint32_t*)&h1;
        ov.z = *(uint32_t*)&h2; ov.w = *(uint32_t*)&h3;
        *(uint4*)&g_pool_h[g * D3 + c8 * 8] = ov;
    }
}

// ---------------- launch ----------------
extern "C" void kernel_launch(void* const* d_in, const int* in_sizes, int n_in,
                              void* d_out, int out_size)
{
    const float* x     = (const float*)d_in[0];
    const int*   ei    = (const int*)d_in[1];
    const int*   batch = (const int*)d_in[2];
    const float* W1 = (const float*)d_in[3];
    const float* as1 = (const float*)d_in[4];
    const float* ad1 = (const float*)d_in[5];
    const float* b1 = (const float*)d_in[6];
    const float* W2 = (const float*)d_in[7];
    const float* as2 = (const float*)d_in[8];
    const float* ad2 = (const float*)d_in[9];
    const float* b2 = (const float*)d_in[10];
    const float* W3 = (const float*)d_in[11];
    const float* as3 = (const float*)d_in[12];
    const float* ad3 = (const float*)d_in[13];
    const float* b3 = (const float*)d_in[14];
    const float* fc1_w = (const float*)d_in[15];
    const float* fc1_b = (const float*)d_in[16];
    const float* fc2_w = (const float*)d_in[17];
    const float* fc2_b = (const float*)d_in[18];
    float* outp = (float*)d_out;

    cudaFuncSetAttribute(hgemm_ca<0, 0>,
                         cudaFuncAttributeMaxDynamicSharedMemorySize, CA_SMEM_BYTES);
    cudaFuncSetAttribute(hgemm_ca<1, 0>,
                         cudaFuncAttributeMaxDynamicSharedMemorySize, CA_SMEM_BYTES);
    cudaFuncSetAttribute(hgemm_ca<1, 1>,
                         cudaFuncAttributeMaxDynamicSharedMemorySize, CA_SMEM_BYTES);

    zero_counts_kernel<<<(NN + 255) / 256, 256>>>();
    hist_kernel<<<(EE + 255) / 256, 256>>>(ei);
    scan_kernel<<<1, 1024>>>();
    csr_fill_kernel<<<(EE + 255) / 256, 256>>>(ei);
    prep_pack<<<(PREP_TOTAL + 255) / 256, 256>>>(x, W1, W2, W3, fc1_w, fc2_w);
    ws_all<<<(WS_TOTAL * 32 + 255) / 256, 256>>>(W1, as1, ad1, W2, as2, ad2, W3, as3, ad3);

    dim3 blk(256);
    {
        dim3 grid((NP1 + 127) / 128, (NN + 127) / 128);
        hgemm_ca<0, 0><<<grid, blk, CA_SMEM_BYTES>>>(5, 7, nullptr, 2, NN, NP1, K1PAD, nullptr);
        gat_agg_h<HEADS, D1, NP1, 1, 64><<<NN, 64>>>(b1);
    }
    {
        dim3 grid((NP23 + 127) / 128, (NN + 127) / 128);
        hgemm_ca<0, 0><<<grid, blk, CA_SMEM_BYTES>>>(1, 8, nullptr, 2, NN, NP23, D2, nullptr);
        gat_agg_h<HEADS, D2, NP23, 2, 128><<<NN, 128>>>(b2);
    }
    {
        dim3 grid((NP23 + 127) / 128, (NN + 127) / 128);
        hgemm_ca<0, 0><<<grid, blk, CA_SMEM_BYTES>>>(1, 9, nullptr, 2, NN, NP23, D3, nullptr);
        gat_agg_h<1, D3, NP23, 2, 128><<<NN, 128>>>(b3);
    }
    {
        dim3 pg(GG, (D3 / 8 + 127) / 128);
        pool_max<<<pg, 128>>>(batch);
        dim3 g1((HID + 127) / 128, (GG + 127) / 128);
        hgemm_ca<1, 0><<<g1, blk, CA_SMEM_BYTES>>>(3, 10, nullptr, 4, GG, HID, D3, fc1_b);
        dim3 g2((OUTD + 127) / 128, (GG + 127) / 128);
        hgemm_ca<1, 1><<<g2, blk, CA_SMEM_BYTES>>>(4, 11, outp, 0, GG, OUTD, HID, fc2_b);
    }
    (void)n_in; (void)in_sizes; (void)out_size;
}